// round 16
// baseline (speedup 1.0000x reference)
#include <cuda_runtime.h>
#include <cuda_fp16.h>
#include <math.h>
#include <stdint.h>

// ---------------- problem constants ----------------
#define NCH   200
#define TLEN  1024
#define MD    512
#define NB    32
#define KPAD  640          // 600 real + 40 zeros = 10 uniform chunks of 64

// ---------------- tiling ----------------
#define TILE_M 128
#define TILE_N 256
#define KCH    64
#define NCHUNK 10
#define NSTAGE 3
#define NTHR   512
// swizzled smem: 128B rows, XOR bank swizzle (no padding)
#define A_O    0
#define A_BYTES (128 * 128)                // 16384
#define B_O    A_BYTES
#define B_BYTES (256 * 128)                // 32768
#define STAGE_BYTES (A_BYTES + B_BYTES)    // 49152
#define SMEM_TOTAL  (NSTAGE * STAGE_BYTES) // 147456/CTA -> 1 CTA/SM

// ---------------- device scratch (bss) ----------------
__device__ __half g_A[4096 * KPAD];
__device__ __half g_B[(size_t)NB * TLEN * KPAD];

// ---------------- PTX helpers (baseline PTX, compute_103-safe) ----------------
__device__ __forceinline__ uint32_t s2u(const void* p) {
    uint32_t a;
    asm("{ .reg .u64 t; cvta.to.shared.u64 t, %1; cvt.u32.u64 %0, t; }" : "=r"(a) : "l"(p));
    return a;
}
#define CPASYNC16(dst, src) \
    asm volatile("cp.async.cg.shared.global [%0], [%1], 16;" :: "r"(dst), "l"(src) : "memory")
#define CP_COMMIT() asm volatile("cp.async.commit_group;" ::: "memory")
#define CP_WAIT(n)  asm volatile("cp.async.wait_group %0;" :: "n"(n) : "memory")

__device__ __forceinline__ void ldsm_x4(uint32_t* r, uint32_t addr) {
    asm volatile("ldmatrix.sync.aligned.m8n8.x4.shared.b16 {%0,%1,%2,%3}, [%4];"
        : "=r"(r[0]), "=r"(r[1]), "=r"(r[2]), "=r"(r[3]) : "r"(addr));
}
__device__ __forceinline__ void mma16816h(float* c, const uint32_t* a, const uint32_t* b) {
    asm volatile("mma.sync.aligned.m16n8k16.row.col.f32.f16.f16.f32 "
        "{%0,%1,%2,%3}, {%4,%5,%6,%7}, {%8,%9}, {%0,%1,%2,%3};"
        : "+f"(c[0]), "+f"(c[1]), "+f"(c[2]), "+f"(c[3])
        : "r"(a[0]), "r"(a[1]), "r"(a[2]), "r"(a[3]), "r"(b[0]), "r"(b[1]));
}

// exact-erf GELU via A&S 7.1.26 (|err_erf| <= 1.5e-7) + fast exp
__device__ __forceinline__ float gelu_fast(float z) {
    float u = fabsf(z) * 0.70710678118654752f;
    float t = __fdividef(1.0f, fmaf(0.3275911f, u, 1.0f));
    float p =               1.061405429f;
    p = fmaf(p, t, -1.453152027f);
    p = fmaf(p, t,  1.421413741f);
    p = fmaf(p, t, -0.284496736f);
    p = fmaf(p, t,  0.254829592f);
    p = p * t;
    float erfc_u = p * __expf(-u * u);
    float erf_s  = copysignf(1.0f - erfc_u, z);
    return 0.5f * z * (1.0f + erf_s);
}

// ---------------- prep kernels (unchanged from R15) ----------------
__global__ void prep_w(const float* __restrict__ W) {
    int p = blockIdx.x * 256 + threadIdx.x;            // quad index < 4096*160
    int idx = p * 4;
    int m = idx / KPAD, k = idx - m * KPAD;
    __half2 h01, h23;
    if (k < 600) {
        float4 v = *(const float4*)(W + m * 768 + k);  // 16B-aligned
        h01.x = __float2half_rn(v.x); h01.y = __float2half_rn(v.y);
        h23.x = __float2half_rn(v.z); h23.y = __float2half_rn(v.w);
    } else {
        h01.x = h01.y = h23.x = h23.y = __float2half_rn(0.0f);
    }
    *(__half2*)&g_A[idx]     = h01;
    *(__half2*)&g_A[idx + 2] = h23;
}

__global__ void prep_x(const float* __restrict__ x) {
    __shared__ float xs[50][68];
    const int b = blockIdx.y, t0 = blockIdx.x * 64;
    const int tid = threadIdx.x;
    const float* xb = x + (size_t)b * NCH * TLEN;
    const size_t Bbase = ((size_t)b * TLEN + t0) * KPAD;

    const __half2 z2 = { __float2half_rn(0.0f), __float2half_rn(0.0f) };
    for (int i = tid; i < 64 * 20; i += 256) {
        int tl = i / 20, q = i - tl * 20;
        *(__half2*)&g_B[Bbase + (size_t)tl * KPAD + 600 + q * 2] = z2;
    }

    for (int cc = 0; cc < 4; cc++) {
        const int c0 = cc * 50;
        __syncthreads();
        for (int i = tid; i < 50 * 66; i += 256) {
            int r = i / 66, col = i - r * 66;
            int gt = t0 - 1 + col;
            xs[r][col] = (gt >= 0 && gt < TLEN) ? xb[(size_t)(c0 + r) * TLEN + gt] : 0.0f;
        }
        __syncthreads();
        for (int i = tid; i < 64 * 75; i += 256) {
            int tl = i / 75, j = i - tl * 75;
            int dk0 = 2 * j;
            int cl0 = dk0 / 3,       kk0 = dk0 - cl0 * 3;
            int cl1 = (dk0 + 1) / 3, kk1 = (dk0 + 1) - cl1 * 3;
            __half2 hh;
            hh.x = __float2half_rn(xs[cl0][tl + kk0]);
            hh.y = __float2half_rn(xs[cl1][tl + kk1]);
            *(__half2*)&g_B[Bbase + (size_t)tl * KPAD + (c0 * 3 + dk0)] = hh;
        }
    }
}

// ---------------- stage copy: swizzled 128B rows (A 128 rows + B 256 rows) ----------------
__device__ __forceinline__ void copy_stage(uint32_t sb,
        const __half* __restrict__ A, const __half* __restrict__ B,
        int k0, int tid) {
    #pragma unroll
    for (int i = 0; i < 2; i++) {              // A: 128 rows x 8 x 16B = 1024 segs
        int v = tid + i * NTHR;
        int row = v >> 3, seg = v & 7;
        uint32_t dst = sb + A_O + row * 128 + ((seg ^ (row & 7)) << 4);
        CPASYNC16(dst, A + (size_t)row * KPAD + k0 + seg * 8);
    }
    #pragma unroll
    for (int i = 0; i < 4; i++) {              // B: 256 rows x 8 x 16B = 2048 segs
        int v = tid + i * NTHR;
        int row = v >> 3, seg = v & 7;
        uint32_t dst = sb + B_O + row * 128 + ((seg ^ (row & 7)) << 4);
        CPASYNC16(dst, B + (size_t)row * KPAD + k0 + seg * 8);
    }
}

// ---------------- main HMMA kernel: 128x256 tile, 4m x 4n warps (32x64 each) ----------------
__global__ __launch_bounds__(NTHR, 1)
void dsmain(const int* __restrict__ did_arr,
            const float* __restrict__ bias,
            float* __restrict__ out) {
    extern __shared__ __half sm[];
    const uint32_t sbase = s2u(sm);
    const int tid = threadIdx.x, wid = tid >> 5, lane = tid & 31;
    const int wmi = wid >> 2, wni = wid & 3;   // warp grid 4(m,32 rows) x 4(n,64 cols)
    const int t0 = blockIdx.x * TILE_N, m0 = blockIdx.y * TILE_M, b = blockIdx.z;
    const int did = did_arr[b];

    const __half* A = g_A + (size_t)(did * MD + m0) * KPAD;
    const __half* B = g_B + ((size_t)b * TLEN + t0) * KPAD;

    // per-lane ldmatrix bases (swizzled layout); row&7 == lane&7 for both A and B
    const uint32_t r7 = (uint32_t)(lane & 7) << 4;
    uint32_t a_base[2], a_k, b_base[4], b_k;
    {
        int tl = lane >> 3, sub = lane & 7;
        a_k = (uint32_t)(tl >> 1) << 4;                  // A groups: (k0,m0-7),(k0,m8-15),(k8,..),(k8,..)
        int mrow = wmi * 32 + (tl & 1) * 8 + sub;
        #pragma unroll
        for (int mt = 0; mt < 2; mt++)
            a_base[mt] = A_O + (mrow + mt * 16) * 128;
        b_k = (uint32_t)(tl & 1) << 4;                   // B groups: (n0-7,k0),(n0-7,k8),(n8-15,k0),(n8-15,k8)
        #pragma unroll
        for (int p = 0; p < 4; p++) {
            int nr = wni * 64 + p * 16 + sub + ((tl >> 1) << 3);
            b_base[p] = B_O + nr * 128;
        }
    }

    float acc[2][8][4];
    #pragma unroll
    for (int i = 0; i < 2; i++)
        #pragma unroll
        for (int j = 0; j < 8; j++)
            #pragma unroll
            for (int q = 0; q < 4; q++) acc[i][j][q] = 0.0f;

    // prologue: fill 2 stages
    copy_stage(sbase,               A, B, 0,   tid); CP_COMMIT();
    copy_stage(sbase + STAGE_BYTES, A, B, KCH, tid); CP_COMMIT();

    int sidx = 0;
    for (int c = 0; c < NCHUNK; c++) {
        if (c == NCHUNK - 1) { CP_WAIT(0); } else { CP_WAIT(1); }
        __syncthreads();   // also fences reuse of stage (c+2)%3 (last read at c-1)

        if (c + 2 < NCHUNK) {
            copy_stage(sbase + ((c + 2) % NSTAGE) * STAGE_BYTES, A, B,
                       (c + 2) * KCH, tid);
            CP_COMMIT();
        }

        const uint32_t sb = sbase + sidx * STAGE_BYTES;
        #pragma unroll
        for (int ks = 0; ks < 4; ks++) {
            const uint32_t ko = ks * 32;       // byte offset within 128B row
            uint32_t bf[4][4], af[2][4];
            #pragma unroll
            for (int p = 0; p < 4; p++)
                ldsm_x4(bf[p], sb + b_base[p] + ((b_k + ko) ^ r7));
            #pragma unroll
            for (int mt = 0; mt < 2; mt++)
                ldsm_x4(af[mt], sb + a_base[mt] + ((a_k + ko) ^ r7));
            #pragma unroll
            for (int mt = 0; mt < 2; mt++)
                #pragma unroll
                for (int nb = 0; nb < 4; nb++)
                    #pragma unroll
                    for (int nn = 0; nn < 2; nn++)
                        mma16816h(acc[mt][nb * 2 + nn], af[mt], &bf[nb][nn * 2]);
        }
        sidx = (sidx == NSTAGE - 1) ? 0 : sidx + 1;
    }

    // ---- epilogue: bias + fast exact GELU ----
    const float* brow = bias + did * MD + m0 + wmi * 32;
    const int rsub = lane >> 2;
    const int csub = (lane & 3) * 2;
    #pragma unroll
    for (int mt = 0; mt < 2; mt++) {
        const float bv0 = brow[mt * 16 + rsub];
        const float bv1 = brow[mt * 16 + rsub + 8];
        float* o0 = out + ((size_t)(b * MD + m0 + wmi * 32 + mt * 16 + rsub)) * TLEN
                        + t0 + wni * 64 + csub;
        float* o1 = o0 + 8 * TLEN;
        #pragma unroll
        for (int j = 0; j < 8; j++) {
            float2 p0, p1;
            p0.x = gelu_fast(acc[mt][j][0] + bv0);
            p0.y = gelu_fast(acc[mt][j][1] + bv0);
            p1.x = gelu_fast(acc[mt][j][2] + bv1);
            p1.y = gelu_fast(acc[mt][j][3] + bv1);
            *(float2*)(o0 + j * 8) = p0;
            *(float2*)(o1 + j * 8) = p1;
        }
    }
}

// ---------------- launch ----------------
extern "C" void kernel_launch(void* const* d_in, const int* in_sizes, int n_in,
                              void* d_out, int out_size) {
    const float* x    = (const float*)d_in[0];   // [32, 200, 1024]
    const int*   did  = (const int*)  d_in[1];   // [32]
    const float* W    = (const float*)d_in[2];   // [4096, 256, 3]
    const float* bias = (const float*)d_in[3];   // [4096]
    float*       out  = (float*)d_out;           // [32, 512, 1024]

    cudaFuncSetAttribute(dsmain, cudaFuncAttributeMaxDynamicSharedMemorySize, SMEM_TOTAL);

    prep_w<<<(4096 * KPAD / 4) / 256, 256>>>(W);
    prep_x<<<dim3(TLEN / 64, NB), 256>>>(x);
    dsmain<<<dim3(TLEN / TILE_N, MD / TILE_M, NB), NTHR, SMEM_TOTAL>>>(did, bias, out);
}

// round 17
// speedup vs baseline: 1.1679x; 1.1679x over previous
#include <cuda_runtime.h>
#include <cuda_fp16.h>
#include <math.h>
#include <stdint.h>

// ---------------- problem constants ----------------
#define NCH   200
#define TLEN  1024
#define MD    512
#define NB    32
#define KPAD  640          // 600 real + 40 zeros = 10 uniform chunks of 64

// ---------------- tiling (R15-proven geometry) ----------------
#define TILE_M 128
#define TILE_N 128
#define KCH    64
#define NCHUNK 10
#define NSTAGE 3
// swizzled smem: 128B rows, XOR bank swizzle (no padding)
#define A_O    0
#define A_BYTES (128 * 128)                // 16384
#define B_O    A_BYTES
#define B_BYTES (128 * 128)                // 16384
#define STAGE_BYTES (A_BYTES + B_BYTES)    // 32768
#define SMEM_TOTAL  (NSTAGE * STAGE_BYTES) // 98304/CTA -> 2 CTAs/SM (192KB)

// ---------------- device scratch (bss) ----------------
__device__ __half g_A[4096 * KPAD];
__device__ __half g_B[(size_t)NB * TLEN * KPAD];

// ---------------- PTX helpers (baseline PTX, compute_103-safe) ----------------
__device__ __forceinline__ uint32_t s2u(const void* p) {
    uint32_t a;
    asm("{ .reg .u64 t; cvta.to.shared.u64 t, %1; cvt.u32.u64 %0, t; }" : "=r"(a) : "l"(p));
    return a;
}
#define CPASYNC16(dst, src) \
    asm volatile("cp.async.cg.shared.global [%0], [%1], 16;" :: "r"(dst), "l"(src) : "memory")
#define CP_COMMIT() asm volatile("cp.async.commit_group;" ::: "memory")
#define CP_WAIT(n)  asm volatile("cp.async.wait_group %0;" :: "n"(n) : "memory")

__device__ __forceinline__ void ldsm_x4(uint32_t* r, uint32_t addr) {
    asm volatile("ldmatrix.sync.aligned.m8n8.x4.shared.b16 {%0,%1,%2,%3}, [%4];"
        : "=r"(r[0]), "=r"(r[1]), "=r"(r[2]), "=r"(r[3]) : "r"(addr));
}
__device__ __forceinline__ void mma16816h(float* c, const uint32_t* a, const uint32_t* b) {
    asm volatile("mma.sync.aligned.m16n8k16.row.col.f32.f16.f16.f32 "
        "{%0,%1,%2,%3}, {%4,%5,%6,%7}, {%8,%9}, {%0,%1,%2,%3};"
        : "+f"(c[0]), "+f"(c[1]), "+f"(c[2]), "+f"(c[3])
        : "r"(a[0]), "r"(a[1]), "r"(a[2]), "r"(a[3]), "r"(b[0]), "r"(b[1]));
}

// exact-erf GELU via A&S 7.1.26 (|err_erf| <= 1.5e-7) + fast exp
__device__ __forceinline__ float gelu_fast(float z) {
    float u = fabsf(z) * 0.70710678118654752f;
    float t = __fdividef(1.0f, fmaf(0.3275911f, u, 1.0f));
    float p =               1.061405429f;
    p = fmaf(p, t, -1.453152027f);
    p = fmaf(p, t,  1.421413741f);
    p = fmaf(p, t, -0.284496736f);
    p = fmaf(p, t,  0.254829592f);
    p = p * t;
    float erfc_u = p * __expf(-u * u);
    float erf_s  = copysignf(1.0f - erfc_u, z);
    return 0.5f * z * (1.0f + erf_s);
}

// ---------------- prep kernels ----------------
// MLP=4: each thread handles one 16-element group (4 x float4 loads, 64B contiguous).
// KPAD/16 = 40 exactly -> groups never straddle an m-row. Max group k = 624 -> reads
// cols <= 639 < 768, always in-bounds within W's row; zero-select per quad for k>=600.
__global__ void prep_w(const float* __restrict__ W) {
    int p = blockIdx.x * 256 + threadIdx.x;            // group index < 4096*40
    int idx = p * 16;
    int m = idx / KPAD, k = idx - m * KPAD;
    const float* wr = W + m * 768 + k;
    float4 v[4];
    #pragma unroll
    for (int q = 0; q < 4; q++)
        v[q] = *(const float4*)(wr + q * 4);           // 4 independent loads in flight
    __half2 h[8];
    #pragma unroll
    for (int q = 0; q < 4; q++) {
        bool ok = (k + q * 4) < 600;
        float x0 = ok ? v[q].x : 0.0f, x1 = ok ? v[q].y : 0.0f;
        float x2 = ok ? v[q].z : 0.0f, x3 = ok ? v[q].w : 0.0f;
        h[q * 2 + 0].x = __float2half_rn(x0); h[q * 2 + 0].y = __float2half_rn(x1);
        h[q * 2 + 1].x = __float2half_rn(x2); h[q * 2 + 1].y = __float2half_rn(x3);
    }
    *(uint4*)&g_A[idx]     = *(uint4*)&h[0];
    *(uint4*)&g_A[idx + 8] = *(uint4*)&h[4];
}

__global__ void prep_x(const float* __restrict__ x) {
    __shared__ float xs[50][68];
    const int b = blockIdx.y, t0 = blockIdx.x * 64;
    const int tid = threadIdx.x;
    const float* xb = x + (size_t)b * NCH * TLEN;
    const size_t Bbase = ((size_t)b * TLEN + t0) * KPAD;

    const __half2 z2 = { __float2half_rn(0.0f), __float2half_rn(0.0f) };
    for (int i = tid; i < 64 * 20; i += 256) {
        int tl = i / 20, q = i - tl * 20;
        *(__half2*)&g_B[Bbase + (size_t)tl * KPAD + 600 + q * 2] = z2;
    }

    for (int cc = 0; cc < 4; cc++) {
        const int c0 = cc * 50;
        __syncthreads();
        for (int i = tid; i < 50 * 66; i += 256) {
            int r = i / 66, col = i - r * 66;
            int gt = t0 - 1 + col;
            xs[r][col] = (gt >= 0 && gt < TLEN) ? xb[(size_t)(c0 + r) * TLEN + gt] : 0.0f;
        }
        __syncthreads();
        for (int i = tid; i < 64 * 75; i += 256) {
            int tl = i / 75, j = i - tl * 75;
            int dk0 = 2 * j;
            int cl0 = dk0 / 3,       kk0 = dk0 - cl0 * 3;
            int cl1 = (dk0 + 1) / 3, kk1 = (dk0 + 1) - cl1 * 3;
            __half2 hh;
            hh.x = __float2half_rn(xs[cl0][tl + kk0]);
            hh.y = __float2half_rn(xs[cl1][tl + kk1]);
            *(__half2*)&g_B[Bbase + (size_t)tl * KPAD + (c0 * 3 + dk0)] = hh;
        }
    }
}

// ---------------- stage copy: swizzled 128B rows (A 128 rows + B 128 rows) ----------------
__device__ __forceinline__ void copy_stage(uint32_t sb,
        const __half* __restrict__ A, const __half* __restrict__ B,
        int k0, int tid) {
    #pragma unroll
    for (int i = 0; i < 4; i++) {              // A: 128 rows x 8 x 16B
        int v = tid + i * 256;
        int row = v >> 3, seg = v & 7;
        uint32_t dst = sb + A_O + row * 128 + ((seg ^ (row & 7)) << 4);
        CPASYNC16(dst, A + (size_t)row * KPAD + k0 + seg * 8);
    }
    #pragma unroll
    for (int i = 0; i < 4; i++) {              // B: 128 rows x 8 x 16B
        int v = tid + i * 256;
        int row = v >> 3, seg = v & 7;
        uint32_t dst = sb + B_O + row * 128 + ((seg ^ (row & 7)) << 4);
        CPASYNC16(dst, B + (size_t)row * KPAD + k0 + seg * 8);
    }
}

// ---------------- main HMMA kernel: 128x128 tile, 4m x 2n warps (32x64 each) ----------------
__global__ __launch_bounds__(256, 2)
void dsmain(const int* __restrict__ did_arr,
            const float* __restrict__ bias,
            float* __restrict__ out) {
    extern __shared__ __half sm[];
    const uint32_t sbase = s2u(sm);
    const int tid = threadIdx.x, wid = tid >> 5, lane = tid & 31;
    const int wmi = wid >> 1, wni = wid & 1;   // warp grid 4(m,32 rows) x 2(n,64 cols)
    const int t0 = blockIdx.x * TILE_N, m0 = blockIdx.y * TILE_M, b = blockIdx.z;
    const int did = did_arr[b];

    const __half* A = g_A + (size_t)(did * MD + m0) * KPAD;
    const __half* B = g_B + ((size_t)b * TLEN + t0) * KPAD;

    // per-lane ldmatrix bases (swizzled layout); row&7 == lane&7 for both A and B
    const uint32_t r7 = (uint32_t)(lane & 7) << 4;
    uint32_t a_base[2], a_k, b_base[4], b_k;
    {
        int tl = lane >> 3, sub = lane & 7;
        a_k = (uint32_t)(tl >> 1) << 4;                  // A groups: (k0,m0-7),(k0,m8-15),(k8,..),(k8,..)
        int mrow = wmi * 32 + (tl & 1) * 8 + sub;
        #pragma unroll
        for (int mt = 0; mt < 2; mt++)
            a_base[mt] = A_O + (mrow + mt * 16) * 128;
        b_k = (uint32_t)(tl & 1) << 4;                   // B groups: (n0-7,k0),(n0-7,k8),(n8-15,k0),(n8-15,k8)
        #pragma unroll
        for (int p = 0; p < 4; p++) {
            int nr = wni * 64 + p * 16 + sub + ((tl >> 1) << 3);
            b_base[p] = B_O + nr * 128;
        }
    }

    float acc[2][8][4];
    #pragma unroll
    for (int i = 0; i < 2; i++)
        #pragma unroll
        for (int j = 0; j < 8; j++)
            #pragma unroll
            for (int q = 0; q < 4; q++) acc[i][j][q] = 0.0f;

    // prologue: fill 2 stages
    copy_stage(sbase,               A, B, 0,   tid); CP_COMMIT();
    copy_stage(sbase + STAGE_BYTES, A, B, KCH, tid); CP_COMMIT();

    int sidx = 0;
    for (int c = 0; c < NCHUNK; c++) {
        if (c == NCHUNK - 1) { CP_WAIT(0); } else { CP_WAIT(1); }
        __syncthreads();   // also fences reuse of stage (c+2)%3 (last read at c-1)

        if (c + 2 < NCHUNK) {
            copy_stage(sbase + ((c + 2) % NSTAGE) * STAGE_BYTES, A, B,
                       (c + 2) * KCH, tid);
            CP_COMMIT();
        }

        const uint32_t sb = sbase + sidx * STAGE_BYTES;
        #pragma unroll
        for (int ks = 0; ks < 4; ks++) {
            const uint32_t ko = ks * 32;       // byte offset within 128B row
            uint32_t bf[4][4], af[2][4];
            #pragma unroll
            for (int p = 0; p < 4; p++)
                ldsm_x4(bf[p], sb + b_base[p] + ((b_k + ko) ^ r7));
            #pragma unroll
            for (int mt = 0; mt < 2; mt++)
                ldsm_x4(af[mt], sb + a_base[mt] + ((a_k + ko) ^ r7));
            #pragma unroll
            for (int mt = 0; mt < 2; mt++)
                #pragma unroll
                for (int nb = 0; nb < 4; nb++)
                    #pragma unroll
                    for (int nn = 0; nn < 2; nn++)
                        mma16816h(acc[mt][nb * 2 + nn], af[mt], &bf[nb][nn * 2]);
        }
        sidx = (sidx == NSTAGE - 1) ? 0 : sidx + 1;
    }

    // ---- epilogue: bias + fast exact GELU, streaming stores (.cs) ----
    const float* brow = bias + did * MD + m0 + wmi * 32;
    const int rsub = lane >> 2;
    const int csub = (lane & 3) * 2;
    #pragma unroll
    for (int mt = 0; mt < 2; mt++) {
        const float bv0 = brow[mt * 16 + rsub];
        const float bv1 = brow[mt * 16 + rsub + 8];
        float* o0 = out + ((size_t)(b * MD + m0 + wmi * 32 + mt * 16 + rsub)) * TLEN
                        + t0 + wni * 64 + csub;
        float* o1 = o0 + 8 * TLEN;
        #pragma unroll
        for (int j = 0; j < 8; j++) {
            float2 p0, p1;
            p0.x = gelu_fast(acc[mt][j][0] + bv0);
            p0.y = gelu_fast(acc[mt][j][1] + bv0);
            p1.x = gelu_fast(acc[mt][j][2] + bv1);
            p1.y = gelu_fast(acc[mt][j][3] + bv1);
            __stcs((float2*)(o0 + j * 8), p0);
            __stcs((float2*)(o1 + j * 8), p1);
        }
    }
}

// ---------------- launch ----------------
extern "C" void kernel_launch(void* const* d_in, const int* in_sizes, int n_in,
                              void* d_out, int out_size) {
    const float* x    = (const float*)d_in[0];   // [32, 200, 1024]
    const int*   did  = (const int*)  d_in[1];   // [32]
    const float* W    = (const float*)d_in[2];   // [4096, 256, 3]
    const float* bias = (const float*)d_in[3];   // [4096]
    float*       out  = (float*)d_out;           // [32, 512, 1024]

    cudaFuncSetAttribute(dsmain, cudaFuncAttributeMaxDynamicSharedMemorySize, SMEM_TOTAL);

    prep_w<<<(4096 * (KPAD / 16)) / 256, 256>>>(W);   // 640 blocks, MLP=4
    prep_x<<<dim3(TLEN / 64, NB), 256>>>(x);
    dsmain<<<dim3(TLEN / TILE_N, MD / TILE_M, NB), 256, SMEM_TOTAL>>>(did, bias, out);
}